// round 1
// baseline (speedup 1.0000x reference)
#include <cuda_runtime.h>
#include <math.h>

// Problem constants
#define Bb   16
#define NPp  512
#define Nn   1024
#define Cc   1024
#define Hh   16
#define HDd  64
#define C3   3072
#define HIDh 4096
#define Mtok 8192   // B*NP

// ---------------- scratch (device globals; no allocation allowed) ----------------
__device__ float g_h   [(size_t)Mtok * Cc];        // LN out (reused for LN1 and LN2)
__device__ float g_qkv [(size_t)Mtok * C3];        // qkv projection
__device__ float g_kf  [(size_t)Bb * Hh * Nn * HDd];
__device__ float g_vf  [(size_t)Bb * Hh * Nn * HDd];
__device__ float g_S   [(size_t)Bb * Hh * NPp * Nn]; // scores -> probs (in place)
__device__ float g_o   [(size_t)Mtok * Cc];        // attention out, token-major
__device__ float g_x1  [(size_t)Mtok * Cc];        // x + proj(o)
__device__ float g_hid [(size_t)Mtok * HIDh];      // MLP hidden
__device__ int   g_p2t [Bb * Nn];                  // pos -> new-token index (or -1)

// ---------------- LayerNorm: one block (256 thr) per row of 1024 ----------------
__global__ void ln_kernel(const float* __restrict__ x, const float* __restrict__ g,
                          const float* __restrict__ b, float* __restrict__ out)
{
    size_t row = blockIdx.x;
    const float* xr = x + row * Cc;
    float* orow = out + row * Cc;
    int t = threadIdx.x;                 // 256 threads, 4 floats each
    float4 v = reinterpret_cast<const float4*>(xr)[t];
    float s  = v.x + v.y + v.z + v.w;
    float ss = v.x*v.x + v.y*v.y + v.z*v.z + v.w*v.w;
    #pragma unroll
    for (int o = 16; o > 0; o >>= 1) {
        s  += __shfl_xor_sync(0xffffffffu, s,  o);
        ss += __shfl_xor_sync(0xffffffffu, ss, o);
    }
    __shared__ float r0[8], r1[8];
    if ((t & 31) == 0) { r0[t >> 5] = s; r1[t >> 5] = ss; }
    __syncthreads();
    s = 0.f; ss = 0.f;
    #pragma unroll
    for (int i = 0; i < 8; i++) { s += r0[i]; ss += r1[i]; }
    float mu  = s * (1.0f / Cc);
    float var = ss * (1.0f / Cc) - mu * mu;
    float inv = rsqrtf(var + 1e-5f);
    float4 gv = reinterpret_cast<const float4*>(g)[t];
    float4 bv = reinterpret_cast<const float4*>(b)[t];
    float4 r;
    r.x = (v.x - mu) * inv * gv.x + bv.x;
    r.y = (v.y - mu) * inv * gv.y + bv.y;
    r.z = (v.z - mu) * inv * gv.z + bv.z;
    r.w = (v.w - mu) * inv * gv.w + bv.w;
    reinterpret_cast<float4*>(orow)[t] = r;
}

// ---------------- mask scan: masked position n -> new-token rank ----------------
__global__ void p2t_kernel(const unsigned* __restrict__ mask)
{
    int b = blockIdx.x;
    if (threadIdx.x == 0) {
        int cnt = 0;
        for (int n = 0; n < Nn; n++) {
            if (mask[b * Nn + n] != 0u) g_p2t[b * Nn + n] = cnt++;
            else                        g_p2t[b * Nn + n] = -1;
        }
    }
}

// ---------------- KV fill: cache copy + scatter of new k/v, one pass ----------------
__global__ void kvfill_kernel(const float* __restrict__ ck, const float* __restrict__ cv)
{
    size_t idx = (size_t)blockIdx.x * blockDim.x + threadIdx.x;  // over B*H*N*HD = 16M
    size_t total = (size_t)Bb * Hh * Nn * HDd;
    if (idx >= total) return;
    int d  = idx & (HDd - 1);
    int n  = (idx >> 6) & (Nn - 1);
    int h  = (idx >> 16) & (Hh - 1);
    int b  = (int)(idx >> 20);
    int tok = g_p2t[b * Nn + n];
    float kv, vv;
    if (tok >= 0) {
        size_t q = ((size_t)(b * NPp + tok)) * C3 + Cc + h * HDd + d;
        kv = g_qkv[q];
        vv = g_qkv[q + Cc];
    } else {
        kv = ck[idx];
        vv = cv[idx];
    }
    g_kf[idx] = kv;
    g_vf[idx] = vv;
}

// ---------------- softmax over rows of 1024 (in place) ----------------
__global__ void softmax_kernel(float* __restrict__ S)
{
    size_t row = blockIdx.x;
    float* p = S + row * (size_t)Nn;
    int t = threadIdx.x;                 // 256
    float4 v = reinterpret_cast<float4*>(p)[t];
    float mx = fmaxf(fmaxf(v.x, v.y), fmaxf(v.z, v.w));
    #pragma unroll
    for (int o = 16; o > 0; o >>= 1) mx = fmaxf(mx, __shfl_xor_sync(0xffffffffu, mx, o));
    __shared__ float shm[8], shs[8];
    if ((t & 31) == 0) shm[t >> 5] = mx;
    __syncthreads();
    mx = shm[0];
    #pragma unroll
    for (int i = 1; i < 8; i++) mx = fmaxf(mx, shm[i]);
    float e0 = __expf(v.x - mx), e1 = __expf(v.y - mx);
    float e2 = __expf(v.z - mx), e3 = __expf(v.w - mx);
    float s = e0 + e1 + e2 + e3;
    #pragma unroll
    for (int o = 16; o > 0; o >>= 1) s += __shfl_xor_sync(0xffffffffu, s, o);
    if ((t & 31) == 0) shs[t >> 5] = s;
    __syncthreads();
    s = 0.f;
    #pragma unroll
    for (int i = 0; i < 8; i++) s += shs[i];
    float inv = 1.0f / s;
    v.x = e0 * inv; v.y = e1 * inv; v.z = e2 * inv; v.w = e3 * inv;
    reinterpret_cast<float4*>(p)[t] = v;
}

// ---------------- generic batched tiled SGEMM ----------------
// C = act(alpha * A@B(^T) + bias) + resid.  64x64 block tile, BK=16, 256 thr, 4x4 microtile.
// Batch offsets: off = (z/16)*s1 + (z%16)*s2  (uniform batch => s1 = 16*stride, s2 = stride).
template<bool TRANSB, bool HAS_BIAS, bool GELU_ACT, bool HAS_RES>
__global__ void __launch_bounds__(256) gemm_kernel(
    const float* __restrict__ A, const float* __restrict__ Bm, float* __restrict__ Cm,
    int K, int lda, int ldb, int ldc,
    long sA1, long sA2, long sB1, long sB2, long sC1, long sC2,
    const float* __restrict__ bias, const float* __restrict__ resid, float alpha)
{
    const int BM = 64, BN = 64, BK = 16;
    int z = blockIdx.z;
    A  += (long)(z / Hh) * sA1 + (long)(z % Hh) * sA2;
    Bm += (long)(z / Hh) * sB1 + (long)(z % Hh) * sB2;
    long offC = (long)(z / Hh) * sC1 + (long)(z % Hh) * sC2;
    Cm += offC;
    const float* Rs = HAS_RES ? (resid + offC) : nullptr;

    __shared__ __align__(16) float As[BK][BM + 4];
    __shared__ __align__(16) float Bs[BK][BN + 4];

    int t  = threadIdx.x;
    int tx = t & 15, ty = t >> 4;
    int m0 = blockIdx.y * BM, n0 = blockIdx.x * BN;

    float acc[4][4];
    #pragma unroll
    for (int i = 0; i < 4; i++)
        #pragma unroll
        for (int j = 0; j < 4; j++) acc[i][j] = 0.f;

    for (int k0 = 0; k0 < K; k0 += BK) {
        {   // A tile 64x16, transposed into As[k][m]
            int r = t >> 2, c4 = (t & 3) * 4;
            float4 av = *reinterpret_cast<const float4*>(&A[(size_t)(m0 + r) * lda + k0 + c4]);
            As[c4 + 0][r] = av.x; As[c4 + 1][r] = av.y;
            As[c4 + 2][r] = av.z; As[c4 + 3][r] = av.w;
        }
        if (TRANSB) {  // B[n,k] tile 64x16 -> Bs[k][n]
            int r = t >> 2, c4 = (t & 3) * 4;
            float4 bv = *reinterpret_cast<const float4*>(&Bm[(size_t)(n0 + r) * ldb + k0 + c4]);
            Bs[c4 + 0][r] = bv.x; Bs[c4 + 1][r] = bv.y;
            Bs[c4 + 2][r] = bv.z; Bs[c4 + 3][r] = bv.w;
        } else {       // B[k,n] tile 16x64 -> Bs[k][n]
            int r = t >> 4, c4 = (t & 15) * 4;
            float4 bv = *reinterpret_cast<const float4*>(&Bm[(size_t)(k0 + r) * ldb + n0 + c4]);
            *reinterpret_cast<float4*>(&Bs[r][c4]) = bv;
        }
        __syncthreads();
        #pragma unroll
        for (int kk = 0; kk < BK; kk++) {
            float a4[4], b4[4];
            *reinterpret_cast<float4*>(a4) = *reinterpret_cast<const float4*>(&As[kk][ty << 2]);
            *reinterpret_cast<float4*>(b4) = *reinterpret_cast<const float4*>(&Bs[kk][tx << 2]);
            #pragma unroll
            for (int i = 0; i < 4; i++)
                #pragma unroll
                for (int j = 0; j < 4; j++) acc[i][j] += a4[i] * b4[j];
        }
        __syncthreads();
    }

    #pragma unroll
    for (int i = 0; i < 4; i++) {
        int m = m0 + (ty << 2) + i;
        #pragma unroll
        for (int j = 0; j < 4; j++) {
            int n = n0 + (tx << 2) + j;
            float v = acc[i][j] * alpha;
            if (HAS_BIAS) v += bias[n];
            if (GELU_ACT) v = 0.5f * v * (1.0f + erff(v * 0.70710678118654752f));
            if (HAS_RES)  v += Rs[(size_t)m * ldc + n];
            Cm[(size_t)m * ldc + n] = v;
        }
    }
}

// ---------------- launch ----------------
extern "C" void kernel_launch(void* const* d_in, const int* in_sizes, int n_in,
                              void* d_out, int out_size)
{
    const float*    x      = (const float*)   d_in[0];
    const float*    cachek = (const float*)   d_in[1];
    const float*    cachev = (const float*)   d_in[2];
    const unsigned* mask   = (const unsigned*)d_in[3];
    const float*    qkv_w  = (const float*)   d_in[4];
    const float*    qkv_b  = (const float*)   d_in[5];
    const float*    proj_w = (const float*)   d_in[6];
    const float*    proj_b = (const float*)   d_in[7];
    const float*    n1_g   = (const float*)   d_in[8];
    const float*    n1_b   = (const float*)   d_in[9];
    const float*    n2_g   = (const float*)   d_in[10];
    const float*    n2_b   = (const float*)   d_in[11];
    const float*    fc1_w  = (const float*)   d_in[12];
    const float*    fc1_b  = (const float*)   d_in[13];
    const float*    fc2_w  = (const float*)   d_in[14];
    const float*    fc2_b  = (const float*)   d_in[15];
    float* out = (float*)d_out;

    float *h, *qkv, *kf, *vf, *S, *o, *x1, *hid;
    cudaGetSymbolAddress((void**)&h,   g_h);
    cudaGetSymbolAddress((void**)&qkv, g_qkv);
    cudaGetSymbolAddress((void**)&kf,  g_kf);
    cudaGetSymbolAddress((void**)&vf,  g_vf);
    cudaGetSymbolAddress((void**)&S,   g_S);
    cudaGetSymbolAddress((void**)&o,   g_o);
    cudaGetSymbolAddress((void**)&x1,  g_x1);
    cudaGetSymbolAddress((void**)&hid, g_hid);

    // 1. LN1
    ln_kernel<<<Mtok, 256>>>(x, n1_g, n1_b, h);

    // 2. QKV = h @ qkv_w + qkv_b     [8192,1024]@[1024,3072]
    gemm_kernel<false, true, false, false><<<dim3(C3 / 64, Mtok / 64, 1), 256>>>(
        h, qkv_w, qkv, Cc, Cc, C3, C3, 0, 0, 0, 0, 0, 0, qkv_b, nullptr, 1.0f);

    // 3. mask scan
    p2t_kernel<<<Bb, 32>>>(mask);

    // 4. KV full fill (16M elements)
    {
        size_t total = (size_t)Bb * Hh * Nn * HDd;
        kvfill_kernel<<<(unsigned)((total + 255) / 256), 256>>>(cachek, cachev);
    }

    // 5. S = (q*scale) @ k_full^T   per (b,h): [512,64]@[1024,64]^T
    gemm_kernel<true, false, false, false><<<dim3(Nn / 64, NPp / 64, Bb * Hh), 256>>>(
        qkv, kf, S, HDd, C3, HDd, Nn,
        (long)NPp * C3, (long)HDd,                       // A: q inside qkv
        (long)Hh * Nn * HDd, (long)Nn * HDd,             // B: k_full
        (long)Hh * NPp * Nn, (long)NPp * Nn,             // C: scores
        nullptr, nullptr, 0.125f);

    // 6. softmax rows
    softmax_kernel<<<Bb * Hh * NPp, 256>>>(S);

    // 7. O = P @ v_full  per (b,h): [512,1024]@[1024,64], written token-major into g_o
    gemm_kernel<false, false, false, false><<<dim3(1, NPp / 64, Bb * Hh), 256>>>(
        S, vf, o, Nn, Nn, HDd, Cc,
        (long)Hh * NPp * Nn, (long)NPp * Nn,             // A: probs
        (long)Hh * Nn * HDd, (long)Nn * HDd,             // B: v_full
        (long)NPp * Cc, (long)HDd,                       // C: token-major (b,t,h,d)
        nullptr, nullptr, 1.0f);

    // 8. x1 = x + o @ proj_w + proj_b
    gemm_kernel<false, true, false, true><<<dim3(Cc / 64, Mtok / 64, 1), 256>>>(
        o, proj_w, x1, Cc, Cc, Cc, Cc, 0, 0, 0, 0, 0, 0, proj_b, x, 1.0f);

    // 9. LN2
    ln_kernel<<<Mtok, 256>>>(x1, n2_g, n2_b, h);

    // 10. hid = gelu(h @ fc1_w + fc1_b)
    gemm_kernel<false, true, true, false><<<dim3(HIDh / 64, Mtok / 64, 1), 256>>>(
        h, fc1_w, hid, Cc, Cc, HIDh, HIDh, 0, 0, 0, 0, 0, 0, fc1_b, nullptr, 1.0f);

    // 11. out = x1 + hid @ fc2_w + fc2_b
    gemm_kernel<false, true, false, true><<<dim3(Cc / 64, Mtok / 64, 1), 256>>>(
        hid, fc2_w, out, HIDh, HIDh, Cc, Cc, 0, 0, 0, 0, 0, 0, fc2_b, x1, 1.0f);
}

// round 4
// speedup vs baseline: 2.0140x; 2.0140x over previous
#include <cuda_runtime.h>
#include <math.h>
#include <stdint.h>

// Problem constants
#define Bb   16
#define NPp  512
#define Nn   1024
#define Cc   1024
#define Hh   16
#define HDd  64
#define C3   3072
#define HIDh 4096
#define Mtok 8192   // B*NP

// ---------------- scratch (device globals) ----------------
__device__ float g_h   [(size_t)Mtok * Cc];
__device__ float g_qkv [(size_t)Mtok * C3];
__device__ float g_kf  [(size_t)Bb * Hh * Nn * HDd];
__device__ float g_vf  [(size_t)Bb * Hh * Nn * HDd];
__device__ float g_S   [(size_t)Bb * Hh * NPp * Nn];
__device__ float g_o   [(size_t)Mtok * Cc];
__device__ float g_x1  [(size_t)Mtok * Cc];
__device__ float g_hid [(size_t)Mtok * HIDh];
__device__ int   g_p2t [Bb * Nn];

// ---------------- helpers ----------------
__device__ __forceinline__ uint32_t f2tf32(float f) {
    uint32_t u;
    asm("cvt.rna.tf32.f32 %0, %1;" : "=r"(u) : "f"(f));
    return u;
}

__device__ __forceinline__ void mma_tf32(float c[4], const uint32_t a[4], const uint32_t b[2]) {
    asm volatile(
        "mma.sync.aligned.m16n8k8.row.col.f32.tf32.tf32.f32 "
        "{%0,%1,%2,%3}, {%4,%5,%6,%7}, {%8,%9}, {%0,%1,%2,%3};"
        : "+f"(c[0]), "+f"(c[1]), "+f"(c[2]), "+f"(c[3])
        : "r"(a[0]), "r"(a[1]), "r"(a[2]), "r"(a[3]), "r"(b[0]), "r"(b[1]));
}

// ---------------- tf32 mma.sync GEMM ----------------
// C[M,N] = act(alpha * A @ B + bias) + resid
// A: [M,K] row-major (lda).
// TRB=true : B is [K,N] row-major (ldb = N row stride)
// TRB=false: B is [N,K] row-major (ldb = K row stride)
// BM=128, BK=16, BN in {64,128}. 256 threads = 8 warps, warp tile 64 x (BN/4).
template<int BN, bool TRB, bool HAS_BIAS, bool GELU_ACT, bool HAS_RES>
__global__ void __launch_bounds__(256) mma_gemm(
    const float* __restrict__ A, const float* __restrict__ Bm, float* __restrict__ Cm,
    int K, int lda, int ldb, int ldc,
    long sA1, long sA2, long sB1, long sB2, long sC1, long sC2,
    const float* __restrict__ bias, const float* __restrict__ resid, float alpha)
{
    const int BM = 128, BK = 16, LDS_ = BK + 4;   // stride 20 words: conflict-free frag loads
    const int WN = BN / 4, NT = WN / 8;           // per-warp n tiles (m16n8 each)
    const int NB_CNT = (BN * BK) / 256;           // B elems per thread (TRB path)
    const int NB4    = (BN * BK) / 4 / 256;       // B float4 per thread (!TRB path)

    __shared__ uint32_t As[2][BM * LDS_];
    __shared__ uint32_t Bs[2][BN * LDS_];

    int t = threadIdx.x, lane = t & 31, warp = t >> 5;
    int g = lane >> 2, tg = lane & 3;
    int wm = (warp >> 2) * 64, wn = (warp & 3) * WN;

    int z = blockIdx.z;
    A  += (long)(z / Hh) * sA1 + (long)(z % Hh) * sA2;
    Bm += (long)(z / Hh) * sB1 + (long)(z % Hh) * sB2;
    long offC = (long)(z / Hh) * sC1 + (long)(z % Hh) * sC2;
    int m0 = blockIdx.y * BM, n0 = blockIdx.x * BN;
    A += (size_t)m0 * lda;     // *** FIX: block row offset was missing in R3 ***

    float acc[4][NT][4];
    #pragma unroll
    for (int i = 0; i < 4; i++)
        #pragma unroll
        for (int j = 0; j < NT; j++)
            #pragma unroll
            for (int l = 0; l < 4; l++) acc[i][j][l] = 0.f;

    const int arow = t >> 2, ac = (t & 3) * 4;     // A/!TRB-B tile addressing

    // ---- loaders: gmem -> regs ----
    auto ldA = [&](int kt, float4 ra[2]) {
        #pragma unroll
        for (int it = 0; it < 2; it++)
            ra[it] = *reinterpret_cast<const float4*>(
                A + (size_t)(arow + it * 64) * lda + kt * BK + ac);
    };
    auto ldBt = [&](int kt, float rb[NB_CNT]) {     // TRB: B[k][n]
        #pragma unroll
        for (int it = 0; it < NB_CNT; it++) {
            int id = t + it * 256;
            int n = id & (BN - 1), k = id / BN;
            rb[it] = Bm[(size_t)(kt * BK + k) * ldb + n0 + n];
        }
    };
    auto ldBn = [&](int kt, float4 rb[NB4]) {       // !TRB: B[n][k]
        #pragma unroll
        for (int it = 0; it < NB4; it++)
            rb[it] = *reinterpret_cast<const float4*>(
                Bm + (size_t)(n0 + arow + it * 64) * ldb + kt * BK + ac);
    };

    // ---- stores: regs -> smem (tf32) ----
    auto stA = [&](int buf, const float4 ra[2]) {
        #pragma unroll
        for (int it = 0; it < 2; it++) {
            int base = (arow + it * 64) * LDS_ + ac;
            As[buf][base + 0] = f2tf32(ra[it].x);
            As[buf][base + 1] = f2tf32(ra[it].y);
            As[buf][base + 2] = f2tf32(ra[it].z);
            As[buf][base + 3] = f2tf32(ra[it].w);
        }
    };
    auto stBt = [&](int buf, const float rb[NB_CNT]) {
        #pragma unroll
        for (int it = 0; it < NB_CNT; it++) {
            int id = t + it * 256;
            int n = id & (BN - 1), k = id / BN;
            Bs[buf][n * LDS_ + k] = f2tf32(rb[it]);
        }
    };
    auto stBn = [&](int buf, const float4 rb[NB4]) {
        #pragma unroll
        for (int it = 0; it < NB4; it++) {
            int base = (arow + it * 64) * LDS_ + ac;
            Bs[buf][base + 0] = f2tf32(rb[it].x);
            Bs[buf][base + 1] = f2tf32(rb[it].y);
            Bs[buf][base + 2] = f2tf32(rb[it].z);
            Bs[buf][base + 3] = f2tf32(rb[it].w);
        }
    };

    auto compute = [&](int buf) {
        #pragma unroll
        for (int ks = 0; ks < 2; ks++) {
            int k0 = ks * 8;
            uint32_t af[4][4], bf[NT][2];
            #pragma unroll
            for (int mt = 0; mt < 4; mt++) {
                int r = wm + mt * 16 + g;
                af[mt][0] = As[buf][r * LDS_ + k0 + tg];
                af[mt][1] = As[buf][(r + 8) * LDS_ + k0 + tg];
                af[mt][2] = As[buf][r * LDS_ + k0 + tg + 4];
                af[mt][3] = As[buf][(r + 8) * LDS_ + k0 + tg + 4];
            }
            #pragma unroll
            for (int nt = 0; nt < NT; nt++) {
                int c = wn + nt * 8 + g;
                bf[nt][0] = Bs[buf][c * LDS_ + k0 + tg];
                bf[nt][1] = Bs[buf][c * LDS_ + k0 + tg + 4];
            }
            #pragma unroll
            for (int mt = 0; mt < 4; mt++)
                #pragma unroll
                for (int nt = 0; nt < NT; nt++)
                    mma_tf32(acc[mt][nt], af[mt], bf[nt]);
        }
    };

    const int KT = K / BK;
    {   // prologue: tile 0 straight to smem
        float4 ra[2]; ldA(0, ra); stA(0, ra);
        if (TRB) { float rb[NB_CNT]; ldBt(0, rb); stBt(0, rb); }
        else     { float4 rb[NB4];   ldBn(0, rb); stBn(0, rb); }
    }
    __syncthreads();

    for (int kt = 0; kt < KT; kt++) {
        int buf = kt & 1;
        bool pf = (kt + 1 < KT);
        float4 ra[2]; float rbt[NB_CNT]; float4 rbn[NB4];
        if (pf) {
            ldA(kt + 1, ra);
            if (TRB) ldBt(kt + 1, rbt); else ldBn(kt + 1, rbn);
        }
        compute(buf);
        if (pf) {
            stA(buf ^ 1, ra);
            if (TRB) stBt(buf ^ 1, rbt); else stBn(buf ^ 1, rbn);
        }
        __syncthreads();
    }

    // ---- epilogue ----
    #pragma unroll
    for (int mt = 0; mt < 4; mt++) {
        int r0 = m0 + wm + mt * 16 + g;
        #pragma unroll
        for (int nt = 0; nt < NT; nt++) {
            int c = n0 + wn + nt * 8 + 2 * tg;
            #pragma unroll
            for (int half = 0; half < 2; half++) {
                int r = r0 + half * 8;
                float v0 = acc[mt][nt][half * 2 + 0] * alpha;
                float v1 = acc[mt][nt][half * 2 + 1] * alpha;
                if (HAS_BIAS) { v0 += bias[c]; v1 += bias[c + 1]; }
                if (GELU_ACT) {
                    v0 = 0.5f * v0 * (1.0f + erff(v0 * 0.70710678118654752f));
                    v1 = 0.5f * v1 * (1.0f + erff(v1 * 0.70710678118654752f));
                }
                if (HAS_RES) {
                    float2 rv = *reinterpret_cast<const float2*>(
                        resid + offC + (size_t)r * ldc + c);
                    v0 += rv.x; v1 += rv.y;
                }
                float2 ov; ov.x = v0; ov.y = v1;
                *reinterpret_cast<float2*>(Cm + offC + (size_t)r * ldc + c) = ov;
            }
        }
    }
}

// ---------------- LayerNorm ----------------
__global__ void ln_kernel(const float* __restrict__ x, const float* __restrict__ g,
                          const float* __restrict__ b, float* __restrict__ out)
{
    size_t row = blockIdx.x;
    const float* xr = x + row * Cc;
    float* orow = out + row * Cc;
    int t = threadIdx.x;
    float4 v = reinterpret_cast<const float4*>(xr)[t];
    float s  = v.x + v.y + v.z + v.w;
    float ss = v.x*v.x + v.y*v.y + v.z*v.z + v.w*v.w;
    #pragma unroll
    for (int o = 16; o > 0; o >>= 1) {
        s  += __shfl_xor_sync(0xffffffffu, s,  o);
        ss += __shfl_xor_sync(0xffffffffu, ss, o);
    }
    __shared__ float r0[8], r1[8];
    if ((t & 31) == 0) { r0[t >> 5] = s; r1[t >> 5] = ss; }
    __syncthreads();
    s = 0.f; ss = 0.f;
    #pragma unroll
    for (int i = 0; i < 8; i++) { s += r0[i]; ss += r1[i]; }
    float mu  = s * (1.0f / Cc);
    float var = ss * (1.0f / Cc) - mu * mu;
    float inv = rsqrtf(var + 1e-5f);
    float4 gv = reinterpret_cast<const float4*>(g)[t];
    float4 bv = reinterpret_cast<const float4*>(b)[t];
    float4 r;
    r.x = (v.x - mu) * inv * gv.x + bv.x;
    r.y = (v.y - mu) * inv * gv.y + bv.y;
    r.z = (v.z - mu) * inv * gv.z + bv.z;
    r.w = (v.w - mu) * inv * gv.w + bv.w;
    reinterpret_cast<float4*>(orow)[t] = r;
}

// ---------------- mask scan ----------------
__global__ void p2t_kernel(const unsigned* __restrict__ mask)
{
    int b = blockIdx.x;
    if (threadIdx.x == 0) {
        int cnt = 0;
        for (int n = 0; n < Nn; n++) {
            if (mask[b * Nn + n] != 0u) g_p2t[b * Nn + n] = cnt++;
            else                        g_p2t[b * Nn + n] = -1;
        }
    }
}

// ---------------- KV fill (float4) ----------------
__global__ void kvfill_kernel(const float4* __restrict__ ck, const float4* __restrict__ cv)
{
    size_t idx = (size_t)blockIdx.x * blockDim.x + threadIdx.x;   // over 4M float4
    int d4 = idx & 15;
    int n  = (idx >> 4) & (Nn - 1);
    int h  = (idx >> 14) & (Hh - 1);
    int b  = (int)(idx >> 18);
    int tok = g_p2t[b * Nn + n];
    float4 kv, vv;
    if (tok >= 0) {
        const float4* qkv4 = reinterpret_cast<const float4*>(g_qkv);
        size_t q = ((size_t)(b * NPp + tok)) * (C3 / 4) + (Cc / 4) + h * (HDd / 4) + d4;
        kv = qkv4[q];
        vv = qkv4[q + Cc / 4];
    } else {
        kv = ck[idx];
        vv = cv[idx];
    }
    reinterpret_cast<float4*>(g_kf)[idx] = kv;
    reinterpret_cast<float4*>(g_vf)[idx] = vv;
}

// ---------------- softmax ----------------
__global__ void softmax_kernel(float* __restrict__ S)
{
    size_t row = blockIdx.x;
    float* p = S + row * (size_t)Nn;
    int t = threadIdx.x;
    float4 v = reinterpret_cast<float4*>(p)[t];
    float mx = fmaxf(fmaxf(v.x, v.y), fmaxf(v.z, v.w));
    #pragma unroll
    for (int o = 16; o > 0; o >>= 1) mx = fmaxf(mx, __shfl_xor_sync(0xffffffffu, mx, o));
    __shared__ float shm[8], shs[8];
    if ((t & 31) == 0) shm[t >> 5] = mx;
    __syncthreads();
    mx = shm[0];
    #pragma unroll
    for (int i = 1; i < 8; i++) mx = fmaxf(mx, shm[i]);
    float e0 = __expf(v.x - mx), e1 = __expf(v.y - mx);
    float e2 = __expf(v.z - mx), e3 = __expf(v.w - mx);
    float s = e0 + e1 + e2 + e3;
    #pragma unroll
    for (int o = 16; o > 0; o >>= 1) s += __shfl_xor_sync(0xffffffffu, s, o);
    if ((t & 31) == 0) shs[t >> 5] = s;
    __syncthreads();
    s = 0.f;
    #pragma unroll
    for (int i = 0; i < 8; i++) s += shs[i];
    float inv = 1.0f / s;
    v.x = e0 * inv; v.y = e1 * inv; v.z = e2 * inv; v.w = e3 * inv;
    reinterpret_cast<float4*>(p)[t] = v;
}

// ---------------- launch ----------------
extern "C" void kernel_launch(void* const* d_in, const int* in_sizes, int n_in,
                              void* d_out, int out_size)
{
    const float*    x      = (const float*)   d_in[0];
    const float*    cachek = (const float*)   d_in[1];
    const float*    cachev = (const float*)   d_in[2];
    const unsigned* mask   = (const unsigned*)d_in[3];
    const float*    qkv_w  = (const float*)   d_in[4];
    const float*    qkv_b  = (const float*)   d_in[5];
    const float*    proj_w = (const float*)   d_in[6];
    const float*    proj_b = (const float*)   d_in[7];
    const float*    n1_g   = (const float*)   d_in[8];
    const float*    n1_b   = (const float*)   d_in[9];
    const float*    n2_g   = (const float*)   d_in[10];
    const float*    n2_b   = (const float*)   d_in[11];
    const float*    fc1_w  = (const float*)   d_in[12];
    const float*    fc1_b  = (const float*)   d_in[13];
    const float*    fc2_w  = (const float*)   d_in[14];
    const float*    fc2_b  = (const float*)   d_in[15];
    float* out = (float*)d_out;

    float *h, *qkv, *kf, *vf, *S, *o, *x1, *hid;
    cudaGetSymbolAddress((void**)&h,   g_h);
    cudaGetSymbolAddress((void**)&qkv, g_qkv);
    cudaGetSymbolAddress((void**)&kf,  g_kf);
    cudaGetSymbolAddress((void**)&vf,  g_vf);
    cudaGetSymbolAddress((void**)&S,   g_S);
    cudaGetSymbolAddress((void**)&o,   g_o);
    cudaGetSymbolAddress((void**)&x1,  g_x1);
    cudaGetSymbolAddress((void**)&hid, g_hid);

    // 1. LN1
    ln_kernel<<<Mtok, 256>>>(x, n1_g, n1_b, h);

    // 2. QKV = h @ qkv_w + qkv_b     [8192,1024]@[1024,3072]
    mma_gemm<128, true, true, false, false><<<dim3(C3 / 128, Mtok / 128, 1), 256>>>(
        h, qkv_w, qkv, Cc, Cc, C3, C3, 0, 0, 0, 0, 0, 0, qkv_b, nullptr, 1.0f);

    // 3. mask scan
    p2t_kernel<<<Bb, 32>>>(mask);

    // 4. KV full fill
    kvfill_kernel<<<((Bb * Hh * Nn * HDd) / 4) / 256, 256>>>(
        (const float4*)cachek, (const float4*)cachev);

    // 5. S = (q*scale) @ k_full^T   per (b,h): [512,64]@[1024,64]^T
    mma_gemm<128, false, false, false, false><<<dim3(Nn / 128, NPp / 128, Bb * Hh), 256>>>(
        qkv, kf, S, HDd, C3, HDd, Nn,
        (long)NPp * C3, (long)HDd,
        (long)Hh * Nn * HDd, (long)Nn * HDd,
        (long)Hh * NPp * Nn, (long)NPp * Nn,
        nullptr, nullptr, 0.125f);

    // 6. softmax
    softmax_kernel<<<Bb * Hh * NPp, 256>>>(S);

    // 7. O = P @ v_full  per (b,h): [512,1024]@[1024,64]  (B = [K,N] row-major)
    mma_gemm<64, true, false, false, false><<<dim3(1, NPp / 128, Bb * Hh), 256>>>(
        S, vf, o, Nn, Nn, HDd, Cc,
        (long)Hh * NPp * Nn, (long)NPp * Nn,
        (long)Hh * Nn * HDd, (long)Nn * HDd,
        (long)NPp * Cc, (long)HDd,
        nullptr, nullptr, 1.0f);

    // 8. x1 = x + o @ proj_w + proj_b
    mma_gemm<128, true, true, false, true><<<dim3(Cc / 128, Mtok / 128, 1), 256>>>(
        o, proj_w, x1, Cc, Cc, Cc, Cc, 0, 0, 0, 0, 0, 0, proj_b, x, 1.0f);

    // 9. LN2
    ln_kernel<<<Mtok, 256>>>(x1, n2_g, n2_b, h);

    // 10. hid = gelu(h @ fc1_w + fc1_b)
    mma_gemm<128, true, true, true, false><<<dim3(HIDh / 128, Mtok / 128, 1), 256>>>(
        h, fc1_w, hid, Cc, Cc, HIDh, HIDh, 0, 0, 0, 0, 0, 0, fc1_b, nullptr, 1.0f);

    // 11. out = x1 + hid @ fc2_w + fc2_b
    mma_gemm<128, true, true, false, true><<<dim3(Cc / 128, Mtok / 128, 1), 256>>>(
        hid, fc2_w, out, HIDh, HIDh, Cc, Cc, 0, 0, 0, 0, 0, 0, fc2_b, x1, 1.0f);
}

// round 5
// speedup vs baseline: 2.2376x; 1.1110x over previous
#include <cuda_runtime.h>
#include <math.h>
#include <stdint.h>

// Problem constants
#define Bb   16
#define NPp  512
#define Nn   1024
#define Cc   1024
#define Hh   16
#define HDd  64
#define C3   3072
#define HIDh 4096
#define Mtok 8192   // B*NP

// ---------------- scratch (device globals) ----------------
__device__ float g_h   [(size_t)Mtok * Cc];
__device__ float g_qkv [(size_t)Mtok * C3];
__device__ float g_kf  [(size_t)Bb * Hh * Nn * HDd];
__device__ float g_vf  [(size_t)Bb * Hh * Nn * HDd];
__device__ float g_o   [(size_t)Mtok * Cc];
__device__ float g_x1  [(size_t)Mtok * Cc];
__device__ float g_hid [(size_t)Mtok * HIDh];
__device__ int   g_p2t [Bb * Nn];

// ---------------- helpers ----------------
__device__ __forceinline__ uint32_t f2tf32(float f) {
    uint32_t u;
    asm("cvt.rna.tf32.f32 %0, %1;" : "=r"(u) : "f"(f));
    return u;
}
__device__ __forceinline__ void mma_tf32(float c[4], const uint32_t a[4], const uint32_t b[2]) {
    asm volatile(
        "mma.sync.aligned.m16n8k8.row.col.f32.tf32.tf32.f32 "
        "{%0,%1,%2,%3}, {%4,%5,%6,%7}, {%8,%9}, {%0,%1,%2,%3};"
        : "+f"(c[0]), "+f"(c[1]), "+f"(c[2]), "+f"(c[3])
        : "r"(a[0]), "r"(a[1]), "r"(a[2]), "r"(a[3]), "r"(b[0]), "r"(b[1]));
}
__device__ __forceinline__ void cp16(uint32_t saddr, const void* g) {
    asm volatile("cp.async.cg.shared.global [%0], [%1], 16;" :: "r"(saddr), "l"(g));
}
#define CP_COMMIT() asm volatile("cp.async.commit_group;")
#define CP_WAIT(n)  asm volatile("cp.async.wait_group %0;" :: "n"(n))

// ---------------- tf32 mma.sync GEMM (unchanged from R4, with m0 fix) ----------------
template<int BN, bool TRB, bool HAS_BIAS, bool GELU_ACT, bool HAS_RES>
__global__ void __launch_bounds__(256) mma_gemm(
    const float* __restrict__ A, const float* __restrict__ Bm, float* __restrict__ Cm,
    int K, int lda, int ldb, int ldc,
    long sA1, long sA2, long sB1, long sB2, long sC1, long sC2,
    const float* __restrict__ bias, const float* __restrict__ resid, float alpha)
{
    const int BM = 128, BK = 16, LDS_ = BK + 4;
    const int WN = BN / 4, NT = WN / 8;
    const int NB_CNT = (BN * BK) / 256;
    const int NB4    = (BN * BK) / 4 / 256;

    __shared__ uint32_t As[2][BM * LDS_];
    __shared__ uint32_t Bs[2][BN * LDS_];

    int t = threadIdx.x, lane = t & 31, warp = t >> 5;
    int g = lane >> 2, tg = lane & 3;
    int wm = (warp >> 2) * 64, wn = (warp & 3) * WN;

    int z = blockIdx.z;
    A  += (long)(z / Hh) * sA1 + (long)(z % Hh) * sA2;
    Bm += (long)(z / Hh) * sB1 + (long)(z % Hh) * sB2;
    long offC = (long)(z / Hh) * sC1 + (long)(z % Hh) * sC2;
    int m0 = blockIdx.y * BM, n0 = blockIdx.x * BN;
    A += (size_t)m0 * lda;

    float acc[4][NT][4];
    #pragma unroll
    for (int i = 0; i < 4; i++)
        #pragma unroll
        for (int j = 0; j < NT; j++)
            #pragma unroll
            for (int l = 0; l < 4; l++) acc[i][j][l] = 0.f;

    const int arow = t >> 2, ac = (t & 3) * 4;

    auto ldA = [&](int kt, float4 ra[2]) {
        #pragma unroll
        for (int it = 0; it < 2; it++)
            ra[it] = *reinterpret_cast<const float4*>(
                A + (size_t)(arow + it * 64) * lda + kt * BK + ac);
    };
    auto ldBt = [&](int kt, float rb[NB_CNT]) {
        #pragma unroll
        for (int it = 0; it < NB_CNT; it++) {
            int id = t + it * 256;
            int n = id & (BN - 1), k = id / BN;
            rb[it] = Bm[(size_t)(kt * BK + k) * ldb + n0 + n];
        }
    };
    auto ldBn = [&](int kt, float4 rb[NB4]) {
        #pragma unroll
        for (int it = 0; it < NB4; it++)
            rb[it] = *reinterpret_cast<const float4*>(
                Bm + (size_t)(n0 + arow + it * 64) * ldb + kt * BK + ac);
    };
    auto stA = [&](int buf, const float4 ra[2]) {
        #pragma unroll
        for (int it = 0; it < 2; it++) {
            int base = (arow + it * 64) * LDS_ + ac;
            As[buf][base + 0] = f2tf32(ra[it].x);
            As[buf][base + 1] = f2tf32(ra[it].y);
            As[buf][base + 2] = f2tf32(ra[it].z);
            As[buf][base + 3] = f2tf32(ra[it].w);
        }
    };
    auto stBt = [&](int buf, const float rb[NB_CNT]) {
        #pragma unroll
        for (int it = 0; it < NB_CNT; it++) {
            int id = t + it * 256;
            int n = id & (BN - 1), k = id / BN;
            Bs[buf][n * LDS_ + k] = f2tf32(rb[it]);
        }
    };
    auto stBn = [&](int buf, const float4 rb[NB4]) {
        #pragma unroll
        for (int it = 0; it < NB4; it++) {
            int base = (arow + it * 64) * LDS_ + ac;
            Bs[buf][base + 0] = f2tf32(rb[it].x);
            Bs[buf][base + 1] = f2tf32(rb[it].y);
            Bs[buf][base + 2] = f2tf32(rb[it].z);
            Bs[buf][base + 3] = f2tf32(rb[it].w);
        }
    };
    auto compute = [&](int buf) {
        #pragma unroll
        for (int ks = 0; ks < 2; ks++) {
            int k0 = ks * 8;
            uint32_t af[4][4], bf[NT][2];
            #pragma unroll
            for (int mt = 0; mt < 4; mt++) {
                int r = wm + mt * 16 + g;
                af[mt][0] = As[buf][r * LDS_ + k0 + tg];
                af[mt][1] = As[buf][(r + 8) * LDS_ + k0 + tg];
                af[mt][2] = As[buf][r * LDS_ + k0 + tg + 4];
                af[mt][3] = As[buf][(r + 8) * LDS_ + k0 + tg + 4];
            }
            #pragma unroll
            for (int nt = 0; nt < NT; nt++) {
                int c = wn + nt * 8 + g;
                bf[nt][0] = Bs[buf][c * LDS_ + k0 + tg];
                bf[nt][1] = Bs[buf][c * LDS_ + k0 + tg + 4];
            }
            #pragma unroll
            for (int mt = 0; mt < 4; mt++)
                #pragma unroll
                for (int nt = 0; nt < NT; nt++)
                    mma_tf32(acc[mt][nt], af[mt], bf[nt]);
        }
    };

    const int KT = K / BK;
    {
        float4 ra[2]; ldA(0, ra); stA(0, ra);
        if (TRB) { float rb[NB_CNT]; ldBt(0, rb); stBt(0, rb); }
        else     { float4 rb[NB4];   ldBn(0, rb); stBn(0, rb); }
    }
    __syncthreads();

    for (int kt = 0; kt < KT; kt++) {
        int buf = kt & 1;
        bool pf = (kt + 1 < KT);
        float4 ra[2]; float rbt[NB_CNT]; float4 rbn[NB4];
        if (pf) {
            ldA(kt + 1, ra);
            if (TRB) ldBt(kt + 1, rbt); else ldBn(kt + 1, rbn);
        }
        compute(buf);
        if (pf) {
            stA(buf ^ 1, ra);
            if (TRB) stBt(buf ^ 1, rbt); else stBn(buf ^ 1, rbn);
        }
        __syncthreads();
    }

    #pragma unroll
    for (int mt = 0; mt < 4; mt++) {
        int r0 = m0 + wm + mt * 16 + g;
        #pragma unroll
        for (int nt = 0; nt < NT; nt++) {
            int c = n0 + wn + nt * 8 + 2 * tg;
            #pragma unroll
            for (int half = 0; half < 2; half++) {
                int r = r0 + half * 8;
                float v0 = acc[mt][nt][half * 2 + 0] * alpha;
                float v1 = acc[mt][nt][half * 2 + 1] * alpha;
                if (HAS_BIAS) { v0 += bias[c]; v1 += bias[c + 1]; }
                if (GELU_ACT) {
                    v0 = 0.5f * v0 * (1.0f + erff(v0 * 0.70710678118654752f));
                    v1 = 0.5f * v1 * (1.0f + erff(v1 * 0.70710678118654752f));
                }
                if (HAS_RES) {
                    float2 rv = *reinterpret_cast<const float2*>(
                        resid + offC + (size_t)r * ldc + c);
                    v0 += rv.x; v1 += rv.y;
                }
                float2 ov; ov.x = v0; ov.y = v1;
                *reinterpret_cast<float2*>(Cm + offC + (size_t)r * ldc + c) = ov;
            }
        }
    }
}

// ---------------- fused flash attention (tf32 mma.sync) ----------------
// Grid: (NP/128, B*H). 256 threads = 8 warps; warp owns 16 q-rows.
// Reads Q from g_qkv, K/V (pre-rounded to tf32 bits) from g_kf/g_vf.
// Writes O token-major into g_o. Never materializes the score tensor.
__global__ void __launch_bounds__(256) flash_kernel(
    const float* __restrict__ qkv, const float* __restrict__ kf,
    const float* __restrict__ vf, float* __restrict__ o)
{
    extern __shared__ float fsm[];
    const int TW = 68;                    // padded row (words)
    const int KWORDS = 64 * TW;           // 4352 words per K or V tile

    int t = threadIdx.x, lane = t & 31, w = t >> 5;
    int g = lane >> 2, tg = lane & 3;
    int bh = blockIdx.y, b = bh >> 4, h = bh & 15;
    int q0 = blockIdx.x * 128;

    // ---- phase 1: Q tile -> smem (natural [q][hd], pad 68) ----
    const float* Qg = qkv + ((size_t)(b * NPp + q0)) * C3 + h * HDd;
    #pragma unroll
    for (int it = 0; it < 8; it++) {
        int id = t + it * 256;            // 2048 float4
        int r = id >> 4, c4 = (id & 15) * 4;
        float4 v = *reinterpret_cast<const float4*>(Qg + (size_t)r * C3 + c4);
        float* d = fsm + r * TW + c4;
        d[0] = v.x; d[1] = v.y; d[2] = v.z; d[3] = v.w;
    }
    __syncthreads();

    // ---- Q fragments (scaled, tf32) ----
    uint32_t qf[8][4];
    {
        int r0 = w * 16 + g;
        #pragma unroll
        for (int kk = 0; kk < 8; kk++) {
            qf[kk][0] = f2tf32(fsm[r0 * TW + kk * 8 + tg] * 0.125f);
            qf[kk][1] = f2tf32(fsm[(r0 + 8) * TW + kk * 8 + tg] * 0.125f);
            qf[kk][2] = f2tf32(fsm[r0 * TW + kk * 8 + tg + 4] * 0.125f);
            qf[kk][3] = f2tf32(fsm[(r0 + 8) * TW + kk * 8 + tg + 4] * 0.125f);
        }
    }
    __syncthreads();                      // smem now reused for K/V buffers

    const float* Kg = kf + (size_t)bh * Nn * HDd;
    const float* Vg = vf + (size_t)bh * Nn * HDd;

    auto issue_tile = [&](int j, int buf) {
        float* Ks = fsm + buf * (2 * KWORDS);
        float* Vs = Ks + KWORDS;
        const float* kg = Kg + (size_t)j * 64 * HDd;
        const float* vg = Vg + (size_t)j * 64 * HDd;
        #pragma unroll
        for (int it = 0; it < 4; it++) {
            int id = t + it * 256;        // 1024 float4 per matrix
            int r = id >> 4, c4 = (id & 15) * 4;
            cp16((uint32_t)__cvta_generic_to_shared(Ks + r * TW + c4), kg + r * HDd + c4);
            cp16((uint32_t)__cvta_generic_to_shared(Vs + r * TW + c4), vg + r * HDd + c4);
        }
    };

    // online softmax state
    float m_r[2] = {-1e30f, -1e30f};
    float l_r[2] = {0.f, 0.f};
    float o_acc[8][4];
    #pragma unroll
    for (int i = 0; i < 8; i++)
        #pragma unroll
        for (int j = 0; j < 4; j++) o_acc[i][j] = 0.f;

    const unsigned FULL = 0xffffffffu;
    const int srcA = (lane & ~3) | (tg >> 1);
    const int srcB = srcA + 2;

    issue_tile(0, 0);
    CP_COMMIT();

    for (int j = 0; j < Nn / 64; j++) {
        int buf = j & 1;
        if (j + 1 < Nn / 64) { issue_tile(j + 1, buf ^ 1); CP_COMMIT(); CP_WAIT(1); }
        else                 { CP_WAIT(0); }
        __syncthreads();

        const uint32_t* Ku = reinterpret_cast<const uint32_t*>(fsm + buf * (2 * KWORDS));
        const uint32_t* Vu = Ku + KWORDS;

        // ---- S = Q K^T ----
        float s[8][4];
        #pragma unroll
        for (int nt = 0; nt < 8; nt++)
            #pragma unroll
            for (int i = 0; i < 4; i++) s[nt][i] = 0.f;
        #pragma unroll
        for (int kk = 0; kk < 8; kk++) {
            #pragma unroll
            for (int nt = 0; nt < 8; nt++) {
                uint32_t bb[2];
                bb[0] = Ku[(nt * 8 + g) * TW + kk * 8 + tg];
                bb[1] = Ku[(nt * 8 + g) * TW + kk * 8 + tg + 4];
                mma_tf32(s[nt], qf[kk], bb);
            }
        }

        // ---- online softmax ----
        float mn0 = m_r[0], mn1 = m_r[1];
        #pragma unroll
        for (int nt = 0; nt < 8; nt++) {
            mn0 = fmaxf(mn0, fmaxf(s[nt][0], s[nt][1]));
            mn1 = fmaxf(mn1, fmaxf(s[nt][2], s[nt][3]));
        }
        mn0 = fmaxf(mn0, __shfl_xor_sync(FULL, mn0, 1));
        mn0 = fmaxf(mn0, __shfl_xor_sync(FULL, mn0, 2));
        mn1 = fmaxf(mn1, __shfl_xor_sync(FULL, mn1, 1));
        mn1 = fmaxf(mn1, __shfl_xor_sync(FULL, mn1, 2));
        float c0 = __expf(m_r[0] - mn0);
        float c1 = __expf(m_r[1] - mn1);
        m_r[0] = mn0; m_r[1] = mn1;

        float pf_[8][4];
        float rs0 = 0.f, rs1 = 0.f;
        #pragma unroll
        for (int nt = 0; nt < 8; nt++) {
            pf_[nt][0] = __expf(s[nt][0] - mn0);
            pf_[nt][1] = __expf(s[nt][1] - mn0);
            pf_[nt][2] = __expf(s[nt][2] - mn1);
            pf_[nt][3] = __expf(s[nt][3] - mn1);
            rs0 += pf_[nt][0] + pf_[nt][1];
            rs1 += pf_[nt][2] + pf_[nt][3];
        }
        rs0 += __shfl_xor_sync(FULL, rs0, 1); rs0 += __shfl_xor_sync(FULL, rs0, 2);
        rs1 += __shfl_xor_sync(FULL, rs1, 1); rs1 += __shfl_xor_sync(FULL, rs1, 2);
        l_r[0] = l_r[0] * c0 + rs0;
        l_r[1] = l_r[1] * c1 + rs1;
        #pragma unroll
        for (int nt = 0; nt < 8; nt++) {
            o_acc[nt][0] *= c0; o_acc[nt][1] *= c0;
            o_acc[nt][2] *= c1; o_acc[nt][3] *= c1;
        }

        // ---- O += P V  (convert C-layout P -> A-frag per k-step via quad shuffles) ----
        #pragma unroll
        for (int kk2 = 0; kk2 < 8; kk2++) {
            float v0 = pf_[kk2][0], v1 = pf_[kk2][1], v2 = pf_[kk2][2], v3 = pf_[kk2][3];
            float w0 = __shfl_sync(FULL, v0, srcA), w1 = __shfl_sync(FULL, v1, srcA);
            float w2 = __shfl_sync(FULL, v2, srcA), w3 = __shfl_sync(FULL, v3, srcA);
            float y0 = __shfl_sync(FULL, v0, srcB), y1 = __shfl_sync(FULL, v1, srcB);
            float y2 = __shfl_sync(FULL, v2, srcB), y3 = __shfl_sync(FULL, v3, srcB);
            bool odd = (tg & 1);
            uint32_t af[4];
            af[0] = f2tf32(odd ? w1 : w0);
            af[1] = f2tf32(odd ? w3 : w2);
            af[2] = f2tf32(odd ? y1 : y0);
            af[3] = f2tf32(odd ? y3 : y2);
            #pragma unroll
            for (int nt2 = 0; nt2 < 8; nt2++) {
                uint32_t bb[2];
                bb[0] = Vu[(kk2 * 8 + tg) * TW + nt2 * 8 + g];
                bb[1] = Vu[(kk2 * 8 + tg + 4) * TW + nt2 * 8 + g];
                mma_tf32(o_acc[nt2], af, bb);
            }
        }
        __syncthreads();
    }

    // ---- normalize + write O (token-major) ----
    float inv0 = 1.0f / l_r[0], inv1 = 1.0f / l_r[1];
    float* Og = o + ((size_t)(b * NPp + q0 + w * 16 + g)) * Cc + h * HDd;
    #pragma unroll
    for (int nt2 = 0; nt2 < 8; nt2++) {
        int c = nt2 * 8 + 2 * tg;
        float2 r0v; r0v.x = o_acc[nt2][0] * inv0; r0v.y = o_acc[nt2][1] * inv0;
        float2 r1v; r1v.x = o_acc[nt2][2] * inv1; r1v.y = o_acc[nt2][3] * inv1;
        *reinterpret_cast<float2*>(Og + c) = r0v;
        *reinterpret_cast<float2*>(Og + (size_t)8 * Cc + c) = r1v;
    }
}

// ---------------- LayerNorm ----------------
__global__ void ln_kernel(const float* __restrict__ x, const float* __restrict__ g,
                          const float* __restrict__ b, float* __restrict__ out)
{
    size_t row = blockIdx.x;
    const float* xr = x + row * Cc;
    float* orow = out + row * Cc;
    int t = threadIdx.x;
    float4 v = reinterpret_cast<const float4*>(xr)[t];
    float s  = v.x + v.y + v.z + v.w;
    float ss = v.x*v.x + v.y*v.y + v.z*v.z + v.w*v.w;
    #pragma unroll
    for (int o = 16; o > 0; o >>= 1) {
        s  += __shfl_xor_sync(0xffffffffu, s,  o);
        ss += __shfl_xor_sync(0xffffffffu, ss, o);
    }
    __shared__ float r0[8], r1[8];
    if ((t & 31) == 0) { r0[t >> 5] = s; r1[t >> 5] = ss; }
    __syncthreads();
    s = 0.f; ss = 0.f;
    #pragma unroll
    for (int i = 0; i < 8; i++) { s += r0[i]; ss += r1[i]; }
    float mu  = s * (1.0f / Cc);
    float var = ss * (1.0f / Cc) - mu * mu;
    float inv = rsqrtf(var + 1e-5f);
    float4 gv = reinterpret_cast<const float4*>(g)[t];
    float4 bv = reinterpret_cast<const float4*>(b)[t];
    float4 r;
    r.x = (v.x - mu) * inv * gv.x + bv.x;
    r.y = (v.y - mu) * inv * gv.y + bv.y;
    r.z = (v.z - mu) * inv * gv.z + bv.z;
    r.w = (v.w - mu) * inv * gv.w + bv.w;
    reinterpret_cast<float4*>(orow)[t] = r;
}

// ---------------- mask scan ----------------
__global__ void p2t_kernel(const unsigned* __restrict__ mask)
{
    int b = blockIdx.x;
    if (threadIdx.x == 0) {
        int cnt = 0;
        for (int n = 0; n < Nn; n++) {
            if (mask[b * Nn + n] != 0u) g_p2t[b * Nn + n] = cnt++;
            else                        g_p2t[b * Nn + n] = -1;
        }
    }
}

// ---------------- KV fill (float4), pre-rounds to tf32 ----------------
__global__ void kvfill_kernel(const float4* __restrict__ ck, const float4* __restrict__ cv)
{
    size_t idx = (size_t)blockIdx.x * blockDim.x + threadIdx.x;   // over 4M float4
    int d4 = idx & 15;
    int n  = (idx >> 4) & (Nn - 1);
    int h  = (idx >> 14) & (Hh - 1);
    int b  = (int)(idx >> 18);
    int tok = g_p2t[b * Nn + n];
    float4 kv, vv;
    if (tok >= 0) {
        const float4* qkv4 = reinterpret_cast<const float4*>(g_qkv);
        size_t q = ((size_t)(b * NPp + tok)) * (C3 / 4) + (Cc / 4) + h * (HDd / 4) + d4;
        kv = qkv4[q];
        vv = qkv4[q + Cc / 4];
    } else {
        kv = ck[idx];
        vv = cv[idx];
    }
    kv.x = __uint_as_float(f2tf32(kv.x)); kv.y = __uint_as_float(f2tf32(kv.y));
    kv.z = __uint_as_float(f2tf32(kv.z)); kv.w = __uint_as_float(f2tf32(kv.w));
    vv.x = __uint_as_float(f2tf32(vv.x)); vv.y = __uint_as_float(f2tf32(vv.y));
    vv.z = __uint_as_float(f2tf32(vv.z)); vv.w = __uint_as_float(f2tf32(vv.w));
    reinterpret_cast<float4*>(g_kf)[idx] = kv;
    reinterpret_cast<float4*>(g_vf)[idx] = vv;
}

// ---------------- launch ----------------
extern "C" void kernel_launch(void* const* d_in, const int* in_sizes, int n_in,
                              void* d_out, int out_size)
{
    const float*    x      = (const float*)   d_in[0];
    const float*    cachek = (const float*)   d_in[1];
    const float*    cachev = (const float*)   d_in[2];
    const unsigned* mask   = (const unsigned*)d_in[3];
    const float*    qkv_w  = (const float*)   d_in[4];
    const float*    qkv_b  = (const float*)   d_in[5];
    const float*    proj_w = (const float*)   d_in[6];
    const float*    proj_b = (const float*)   d_in[7];
    const float*    n1_g   = (const float*)   d_in[8];
    const float*    n1_b   = (const float*)   d_in[9];
    const float*    n2_g   = (const float*)   d_in[10];
    const float*    n2_b   = (const float*)   d_in[11];
    const float*    fc1_w  = (const float*)   d_in[12];
    const float*    fc1_b  = (const float*)   d_in[13];
    const float*    fc2_w  = (const float*)   d_in[14];
    const float*    fc2_b  = (const float*)   d_in[15];
    float* out = (float*)d_out;

    float *h, *qkv, *kf, *vf, *o, *x1, *hid;
    cudaGetSymbolAddress((void**)&h,   g_h);
    cudaGetSymbolAddress((void**)&qkv, g_qkv);
    cudaGetSymbolAddress((void**)&kf,  g_kf);
    cudaGetSymbolAddress((void**)&vf,  g_vf);
    cudaGetSymbolAddress((void**)&o,   g_o);
    cudaGetSymbolAddress((void**)&x1,  g_x1);
    cudaGetSymbolAddress((void**)&hid, g_hid);

    const int FLASH_SMEM = 2 * 2 * 64 * 68 * 4;   // 69632 bytes
    cudaFuncSetAttribute(flash_kernel,
                         cudaFuncAttributeMaxDynamicSharedMemorySize, FLASH_SMEM);

    // 1. LN1
    ln_kernel<<<Mtok, 256>>>(x, n1_g, n1_b, h);

    // 2. QKV = h @ qkv_w + qkv_b
    mma_gemm<128, true, true, false, false><<<dim3(C3 / 128, Mtok / 128, 1), 256>>>(
        h, qkv_w, qkv, Cc, Cc, C3, C3, 0, 0, 0, 0, 0, 0, qkv_b, nullptr, 1.0f);

    // 3. mask scan
    p2t_kernel<<<Bb, 32>>>(mask);

    // 4. KV full fill (tf32-rounded)
    kvfill_kernel<<<((Bb * Hh * Nn * HDd) / 4) / 256, 256>>>(
        (const float4*)cachek, (const float4*)cachev);

    // 5-7. fused attention
    flash_kernel<<<dim3(NPp / 128, Bb * Hh), 256, FLASH_SMEM>>>(qkv, kf, vf, o);

    // 8. x1 = x + o @ proj_w + proj_b
    mma_gemm<128, true, true, false, true><<<dim3(Cc / 128, Mtok / 128, 1), 256>>>(
        o, proj_w, x1, Cc, Cc, Cc, Cc, 0, 0, 0, 0, 0, 0, proj_b, x, 1.0f);

    // 9. LN2
    ln_kernel<<<Mtok, 256>>>(x1, n2_g, n2_b, h);

    // 10. hid = gelu(h @ fc1_w + fc1_b)
    mma_gemm<128, true, true, true, false><<<dim3(HIDh / 128, Mtok / 128, 1), 256>>>(
        h, fc1_w, hid, Cc, Cc, HIDh, HIDh, 0, 0, 0, 0, 0, 0, fc1_b, nullptr, 1.0f);

    // 11. out = x1 + hid @ fc2_w + fc2_b
    mma_gemm<128, true, true, false, true><<<dim3(Cc / 128, Mtok / 128, 1), 256>>>(
        hid, fc2_w, out, HIDh, HIDh, Cc, Cc, 0, 0, 0, 0, 0, 0, fc2_b, x1, 1.0f);
}

// round 6
// speedup vs baseline: 3.7381x; 1.6706x over previous
#include <cuda_runtime.h>
#include <math.h>
#include <stdint.h>

// Problem constants
#define Bb   16
#define NPp  512
#define Nn   1024
#define Cc   1024
#define Hh   16
#define HDd  64
#define C3   3072
#define HIDh 4096
#define Mtok 8192   // B*NP

// ---------------- scratch (device globals) ----------------
__device__ float g_h   [(size_t)Mtok * Cc];
__device__ float g_qkv [(size_t)Mtok * C3];
__device__ float g_kf  [(size_t)Bb * Hh * Nn * HDd];
__device__ float g_vf  [(size_t)Bb * Hh * Nn * HDd];
__device__ float g_o   [(size_t)Mtok * Cc];
__device__ float g_x1  [(size_t)Mtok * Cc];
__device__ float g_hid [(size_t)Mtok * HIDh];
__device__ int   g_p2t [Bb * Nn];
// tf32-rounded weights
__device__ float g_wq  [(size_t)Cc * C3];
__device__ float g_wp  [(size_t)Cc * Cc];
__device__ float g_w1  [(size_t)Cc * HIDh];
__device__ float g_w2  [(size_t)HIDh * Cc];

// ---------------- helpers ----------------
__device__ __forceinline__ uint32_t f2tf32(float f) {
    uint32_t u;
    asm("cvt.rna.tf32.f32 %0, %1;" : "=r"(u) : "f"(f));
    return u;
}
__device__ __forceinline__ float rnd32(float f) { return __uint_as_float(f2tf32(f)); }

__device__ __forceinline__ void mma_tf32(float c[4], const uint32_t a[4], const uint32_t b[2]) {
    asm volatile(
        "mma.sync.aligned.m16n8k8.row.col.f32.tf32.tf32.f32 "
        "{%0,%1,%2,%3}, {%4,%5,%6,%7}, {%8,%9}, {%0,%1,%2,%3};"
        : "+f"(c[0]), "+f"(c[1]), "+f"(c[2]), "+f"(c[3])
        : "r"(a[0]), "r"(a[1]), "r"(a[2]), "r"(a[3]), "r"(b[0]), "r"(b[1]));
}
__device__ __forceinline__ void cp16(uint32_t saddr, const void* g) {
    asm volatile("cp.async.cg.shared.global [%0], [%1], 16;" :: "r"(saddr), "l"(g));
}
#define CP_COMMIT() asm volatile("cp.async.commit_group;")
#define CP_WAIT(n)  asm volatile("cp.async.wait_group %0;" :: "n"(n))

// ---------------- weight pre-round ----------------
__global__ void round_kernel(const float4* __restrict__ in, float4* __restrict__ outp)
{
    size_t i = (size_t)blockIdx.x * blockDim.x + threadIdx.x;
    float4 v = in[i];
    v.x = rnd32(v.x); v.y = rnd32(v.y); v.z = rnd32(v.z); v.w = rnd32(v.w);
    outp[i] = v;
}

// ---------------- tf32 mma.sync GEMM, cp.async 3-stage ----------------
// C[M,N] = act(A @ B + bias) + resid ;  A:[M,K] row-major, B:[K,N] row-major.
// Inputs MUST be pre-rounded to tf32. BM=128, BN=128, BK=16, 256 thr (8 warps, 64x32 tiles).
template<bool HAS_BIAS, bool GELU_ACT, bool HAS_RES, bool ROUND_OUT>
__global__ void __launch_bounds__(256) mma_gemm(
    const float* __restrict__ A, const float* __restrict__ Bm, float* __restrict__ Cm,
    int K, int lda, int ldb, int ldc,
    const float* __restrict__ bias, const float* __restrict__ resid)
{
    const int AW = 20, BW = 136;                 // smem row strides (words)
    const int AWORDS = 128 * AW, BWORDS = 16 * BW;
    const int STW = AWORDS + BWORDS;             // 4736 words per stage

    extern __shared__ float sm[];

    int t = threadIdx.x, lane = t & 31, warp = t >> 5;
    int g = lane >> 2, tg = lane & 3;
    int wm = (warp >> 2) * 64, wn = (warp & 3) * 32;
    int m0 = blockIdx.y * 128, n0 = blockIdx.x * 128;

    const float* Ab = A + (size_t)m0 * lda;
    const float* Bb_ = Bm + n0;

    float acc[4][4][4];
    #pragma unroll
    for (int i = 0; i < 4; i++)
        #pragma unroll
        for (int j = 0; j < 4; j++)
            #pragma unroll
            for (int l = 0; l < 4; l++) acc[i][j][l] = 0.f;

    auto issue = [&](int kt, int st) {
        float* As = sm + st * STW;
        float* Bs = As + AWORDS;
        const float* Ag = Ab + kt * 16;
        const float* Bg = Bb_ + (size_t)(kt * 16) * ldb;
        #pragma unroll
        for (int it = 0; it < 2; it++) {
            int c = t + it * 256;
            int r = c >> 2, c4 = (c & 3) * 4;
            cp16((uint32_t)__cvta_generic_to_shared(As + r * AW + c4),
                 Ag + (size_t)r * lda + c4);
        }
        #pragma unroll
        for (int it = 0; it < 2; it++) {
            int c = t + it * 256;
            int k = c >> 5, n4 = (c & 31) * 4;
            cp16((uint32_t)__cvta_generic_to_shared(Bs + k * BW + n4),
                 Bg + (size_t)k * ldb + n4);
        }
        CP_COMMIT();
    };

    auto compute = [&](int st) {
        const uint32_t* As = reinterpret_cast<const uint32_t*>(sm + st * STW);
        const uint32_t* Bs = As + AWORDS;
        #pragma unroll
        for (int ks = 0; ks < 2; ks++) {
            int k0 = ks * 8;
            uint32_t af[4][4], bf[4][2];
            #pragma unroll
            for (int mt = 0; mt < 4; mt++) {
                int r = wm + mt * 16 + g;
                af[mt][0] = As[r * AW + k0 + tg];
                af[mt][1] = As[(r + 8) * AW + k0 + tg];
                af[mt][2] = As[r * AW + k0 + tg + 4];
                af[mt][3] = As[(r + 8) * AW + k0 + tg + 4];
            }
            #pragma unroll
            for (int nt = 0; nt < 4; nt++) {
                int c = wn + nt * 8 + g;
                bf[nt][0] = Bs[(k0 + tg) * BW + c];
                bf[nt][1] = Bs[(k0 + tg + 4) * BW + c];
            }
            #pragma unroll
            for (int mt = 0; mt < 4; mt++)
                #pragma unroll
                for (int nt = 0; nt < 4; nt++)
                    mma_tf32(acc[mt][nt], af[mt], bf[nt]);
        }
    };

    const int KT = K / 16;
    issue(0, 0);
    issue(1, 1);

    for (int kt = 0; kt < KT; kt++) {
        if (kt + 1 < KT) { CP_WAIT(1); } else { CP_WAIT(0); }
        __syncthreads();
        compute(kt % 3);
        if (kt + 2 < KT) issue(kt + 2, (kt + 2) % 3);
    }

    // ---- epilogue ----
    #pragma unroll
    for (int mt = 0; mt < 4; mt++) {
        int r0 = m0 + wm + mt * 16 + g;
        #pragma unroll
        for (int nt = 0; nt < 4; nt++) {
            int c = n0 + wn + nt * 8 + 2 * tg;
            #pragma unroll
            for (int half = 0; half < 2; half++) {
                int r = r0 + half * 8;
                float v0 = acc[mt][nt][half * 2 + 0];
                float v1 = acc[mt][nt][half * 2 + 1];
                if (HAS_BIAS) { v0 += bias[c]; v1 += bias[c + 1]; }
                if (GELU_ACT) {
                    v0 = 0.5f * v0 * (1.0f + erff(v0 * 0.70710678118654752f));
                    v1 = 0.5f * v1 * (1.0f + erff(v1 * 0.70710678118654752f));
                }
                if (HAS_RES) {
                    float2 rv = *reinterpret_cast<const float2*>(
                        resid + (size_t)r * ldc + c);
                    v0 += rv.x; v1 += rv.y;
                }
                if (ROUND_OUT) { v0 = rnd32(v0); v1 = rnd32(v1); }
                float2 ov; ov.x = v0; ov.y = v1;
                *reinterpret_cast<float2*>(Cm + (size_t)r * ldc + c) = ov;
            }
        }
    }
}

// ---------------- fused flash attention (tf32 mma.sync) ----------------
__global__ void __launch_bounds__(256) flash_kernel(
    const float* __restrict__ qkv, const float* __restrict__ kf,
    const float* __restrict__ vf, float* __restrict__ o)
{
    extern __shared__ float fsm[];
    const int TW = 68;
    const int KWORDS = 64 * TW;

    int t = threadIdx.x, lane = t & 31, w = t >> 5;
    int g = lane >> 2, tg = lane & 3;
    int bh = blockIdx.y, b = bh >> 4, h = bh & 15;
    int q0 = blockIdx.x * 128;

    const float* Qg = qkv + ((size_t)(b * NPp + q0)) * C3 + h * HDd;
    #pragma unroll
    for (int it = 0; it < 8; it++) {
        int id = t + it * 256;
        int r = id >> 4, c4 = (id & 15) * 4;
        float4 v = *reinterpret_cast<const float4*>(Qg + (size_t)r * C3 + c4);
        float* d = fsm + r * TW + c4;
        d[0] = v.x; d[1] = v.y; d[2] = v.z; d[3] = v.w;
    }
    __syncthreads();

    uint32_t qf[8][4];
    {
        int r0 = w * 16 + g;
        #pragma unroll
        for (int kk = 0; kk < 8; kk++) {
            qf[kk][0] = f2tf32(fsm[r0 * TW + kk * 8 + tg] * 0.125f);
            qf[kk][1] = f2tf32(fsm[(r0 + 8) * TW + kk * 8 + tg] * 0.125f);
            qf[kk][2] = f2tf32(fsm[r0 * TW + kk * 8 + tg + 4] * 0.125f);
            qf[kk][3] = f2tf32(fsm[(r0 + 8) * TW + kk * 8 + tg + 4] * 0.125f);
        }
    }
    __syncthreads();

    const float* Kg = kf + (size_t)bh * Nn * HDd;
    const float* Vg = vf + (size_t)bh * Nn * HDd;

    auto issue_tile = [&](int j, int buf) {
        float* Ks = fsm + buf * (2 * KWORDS);
        float* Vs = Ks + KWORDS;
        const float* kg = Kg + (size_t)j * 64 * HDd;
        const float* vg = Vg + (size_t)j * 64 * HDd;
        #pragma unroll
        for (int it = 0; it < 4; it++) {
            int id = t + it * 256;
            int r = id >> 4, c4 = (id & 15) * 4;
            cp16((uint32_t)__cvta_generic_to_shared(Ks + r * TW + c4), kg + r * HDd + c4);
            cp16((uint32_t)__cvta_generic_to_shared(Vs + r * TW + c4), vg + r * HDd + c4);
        }
    };

    float m_r[2] = {-1e30f, -1e30f};
    float l_r[2] = {0.f, 0.f};
    float o_acc[8][4];
    #pragma unroll
    for (int i = 0; i < 8; i++)
        #pragma unroll
        for (int j = 0; j < 4; j++) o_acc[i][j] = 0.f;

    const unsigned FULL = 0xffffffffu;
    const int srcA = (lane & ~3) | (tg >> 1);
    const int srcB = srcA + 2;

    issue_tile(0, 0);
    CP_COMMIT();

    for (int j = 0; j < Nn / 64; j++) {
        int buf = j & 1;
        if (j + 1 < Nn / 64) { issue_tile(j + 1, buf ^ 1); CP_COMMIT(); CP_WAIT(1); }
        else                 { CP_WAIT(0); }
        __syncthreads();

        const uint32_t* Ku = reinterpret_cast<const uint32_t*>(fsm + buf * (2 * KWORDS));
        const uint32_t* Vu = Ku + KWORDS;

        float s[8][4];
        #pragma unroll
        for (int nt = 0; nt < 8; nt++)
            #pragma unroll
            for (int i = 0; i < 4; i++) s[nt][i] = 0.f;
        #pragma unroll
        for (int kk = 0; kk < 8; kk++) {
            #pragma unroll
            for (int nt = 0; nt < 8; nt++) {
                uint32_t bb[2];
                bb[0] = Ku[(nt * 8 + g) * TW + kk * 8 + tg];
                bb[1] = Ku[(nt * 8 + g) * TW + kk * 8 + tg + 4];
                mma_tf32(s[nt], qf[kk], bb);
            }
        }

        float mn0 = m_r[0], mn1 = m_r[1];
        #pragma unroll
        for (int nt = 0; nt < 8; nt++) {
            mn0 = fmaxf(mn0, fmaxf(s[nt][0], s[nt][1]));
            mn1 = fmaxf(mn1, fmaxf(s[nt][2], s[nt][3]));
        }
        mn0 = fmaxf(mn0, __shfl_xor_sync(FULL, mn0, 1));
        mn0 = fmaxf(mn0, __shfl_xor_sync(FULL, mn0, 2));
        mn1 = fmaxf(mn1, __shfl_xor_sync(FULL, mn1, 1));
        mn1 = fmaxf(mn1, __shfl_xor_sync(FULL, mn1, 2));
        float c0 = __expf(m_r[0] - mn0);
        float c1 = __expf(m_r[1] - mn1);
        m_r[0] = mn0; m_r[1] = mn1;

        float pf_[8][4];
        float rs0 = 0.f, rs1 = 0.f;
        #pragma unroll
        for (int nt = 0; nt < 8; nt++) {
            pf_[nt][0] = __expf(s[nt][0] - mn0);
            pf_[nt][1] = __expf(s[nt][1] - mn0);
            pf_[nt][2] = __expf(s[nt][2] - mn1);
            pf_[nt][3] = __expf(s[nt][3] - mn1);
            rs0 += pf_[nt][0] + pf_[nt][1];
            rs1 += pf_[nt][2] + pf_[nt][3];
        }
        rs0 += __shfl_xor_sync(FULL, rs0, 1); rs0 += __shfl_xor_sync(FULL, rs0, 2);
        rs1 += __shfl_xor_sync(FULL, rs1, 1); rs1 += __shfl_xor_sync(FULL, rs1, 2);
        l_r[0] = l_r[0] * c0 + rs0;
        l_r[1] = l_r[1] * c1 + rs1;
        #pragma unroll
        for (int nt = 0; nt < 8; nt++) {
            o_acc[nt][0] *= c0; o_acc[nt][1] *= c0;
            o_acc[nt][2] *= c1; o_acc[nt][3] *= c1;
        }

        #pragma unroll
        for (int kk2 = 0; kk2 < 8; kk2++) {
            float v0 = pf_[kk2][0], v1 = pf_[kk2][1], v2 = pf_[kk2][2], v3 = pf_[kk2][3];
            float w0 = __shfl_sync(FULL, v0, srcA), w1 = __shfl_sync(FULL, v1, srcA);
            float w2 = __shfl_sync(FULL, v2, srcA), w3 = __shfl_sync(FULL, v3, srcA);
            float y0 = __shfl_sync(FULL, v0, srcB), y1 = __shfl_sync(FULL, v1, srcB);
            float y2 = __shfl_sync(FULL, v2, srcB), y3 = __shfl_sync(FULL, v3, srcB);
            bool odd = (tg & 1);
            uint32_t af[4];
            af[0] = f2tf32(odd ? w1 : w0);
            af[1] = f2tf32(odd ? w3 : w2);
            af[2] = f2tf32(odd ? y1 : y0);
            af[3] = f2tf32(odd ? y3 : y2);
            #pragma unroll
            for (int nt2 = 0; nt2 < 8; nt2++) {
                uint32_t bb[2];
                bb[0] = Vu[(kk2 * 8 + tg) * TW + nt2 * 8 + g];
                bb[1] = Vu[(kk2 * 8 + tg + 4) * TW + nt2 * 8 + g];
                mma_tf32(o_acc[nt2], af, bb);
            }
        }
        __syncthreads();
    }

    float inv0 = 1.0f / l_r[0], inv1 = 1.0f / l_r[1];
    float* Og = o + ((size_t)(b * NPp + q0 + w * 16 + g)) * Cc + h * HDd;
    #pragma unroll
    for (int nt2 = 0; nt2 < 8; nt2++) {
        int c = nt2 * 8 + 2 * tg;
        float2 r0v; r0v.x = rnd32(o_acc[nt2][0] * inv0); r0v.y = rnd32(o_acc[nt2][1] * inv0);
        float2 r1v; r1v.x = rnd32(o_acc[nt2][2] * inv1); r1v.y = rnd32(o_acc[nt2][3] * inv1);
        *reinterpret_cast<float2*>(Og + c) = r0v;
        *reinterpret_cast<float2*>(Og + (size_t)8 * Cc + c) = r1v;
    }
}

// ---------------- LayerNorm (tf32-rounded output) ----------------
__global__ void ln_kernel(const float* __restrict__ x, const float* __restrict__ g,
                          const float* __restrict__ b, float* __restrict__ out)
{
    size_t row = blockIdx.x;
    const float* xr = x + row * Cc;
    float* orow = out + row * Cc;
    int t = threadIdx.x;
    float4 v = reinterpret_cast<const float4*>(xr)[t];
    float s  = v.x + v.y + v.z + v.w;
    float ss = v.x*v.x + v.y*v.y + v.z*v.z + v.w*v.w;
    #pragma unroll
    for (int o = 16; o > 0; o >>= 1) {
        s  += __shfl_xor_sync(0xffffffffu, s,  o);
        ss += __shfl_xor_sync(0xffffffffu, ss, o);
    }
    __shared__ float r0[8], r1[8];
    if ((t & 31) == 0) { r0[t >> 5] = s; r1[t >> 5] = ss; }
    __syncthreads();
    s = 0.f; ss = 0.f;
    #pragma unroll
    for (int i = 0; i < 8; i++) { s += r0[i]; ss += r1[i]; }
    float mu  = s * (1.0f / Cc);
    float var = ss * (1.0f / Cc) - mu * mu;
    float inv = rsqrtf(var + 1e-5f);
    float4 gv = reinterpret_cast<const float4*>(g)[t];
    float4 bv = reinterpret_cast<const float4*>(b)[t];
    float4 r;
    r.x = rnd32((v.x - mu) * inv * gv.x + bv.x);
    r.y = rnd32((v.y - mu) * inv * gv.y + bv.y);
    r.z = rnd32((v.z - mu) * inv * gv.z + bv.z);
    r.w = rnd32((v.w - mu) * inv * gv.w + bv.w);
    reinterpret_cast<float4*>(orow)[t] = r;
}

// ---------------- mask scan ----------------
__global__ void p2t_kernel(const unsigned* __restrict__ mask)
{
    int b = blockIdx.x;
    if (threadIdx.x == 0) {
        int cnt = 0;
        for (int n = 0; n < Nn; n++) {
            if (mask[b * Nn + n] != 0u) g_p2t[b * Nn + n] = cnt++;
            else                        g_p2t[b * Nn + n] = -1;
        }
    }
}

// ---------------- KV fill (float4), pre-rounds to tf32 ----------------
__global__ void kvfill_kernel(const float4* __restrict__ ck, const float4* __restrict__ cv)
{
    size_t idx = (size_t)blockIdx.x * blockDim.x + threadIdx.x;
    int d4 = idx & 15;
    int n  = (idx >> 4) & (Nn - 1);
    int h  = (idx >> 14) & (Hh - 1);
    int b  = (int)(idx >> 18);
    int tok = g_p2t[b * Nn + n];
    float4 kv, vv;
    if (tok >= 0) {
        const float4* qkv4 = reinterpret_cast<const float4*>(g_qkv);
        size_t q = ((size_t)(b * NPp + tok)) * (C3 / 4) + (Cc / 4) + h * (HDd / 4) + d4;
        kv = qkv4[q];
        vv = qkv4[q + Cc / 4];
    } else {
        kv = ck[idx];
        vv = cv[idx];
    }
    kv.x = rnd32(kv.x); kv.y = rnd32(kv.y); kv.z = rnd32(kv.z); kv.w = rnd32(kv.w);
    vv.x = rnd32(vv.x); vv.y = rnd32(vv.y); vv.z = rnd32(vv.z); vv.w = rnd32(vv.w);
    reinterpret_cast<float4*>(g_kf)[idx] = kv;
    reinterpret_cast<float4*>(g_vf)[idx] = vv;
}

// ---------------- launch ----------------
extern "C" void kernel_launch(void* const* d_in, const int* in_sizes, int n_in,
                              void* d_out, int out_size)
{
    const float*    x      = (const float*)   d_in[0];
    const float*    cachek = (const float*)   d_in[1];
    const float*    cachev = (const float*)   d_in[2];
    const unsigned* mask   = (const unsigned*)d_in[3];
    const float*    qkv_w  = (const float*)   d_in[4];
    const float*    qkv_b  = (const float*)   d_in[5];
    const float*    proj_w = (const float*)   d_in[6];
    const float*    proj_b = (const float*)   d_in[7];
    const float*    n1_g   = (const float*)   d_in[8];
    const float*    n1_b   = (const float*)   d_in[9];
    const float*    n2_g   = (const float*)   d_in[10];
    const float*    n2_b   = (const float*)   d_in[11];
    const float*    fc1_w  = (const float*)   d_in[12];
    const float*    fc1_b  = (const float*)   d_in[13];
    const float*    fc2_w  = (const float*)   d_in[14];
    const float*    fc2_b  = (const float*)   d_in[15];
    float* out = (float*)d_out;

    float *h, *qkv, *kf, *vf, *o, *x1, *hid, *wq, *wp, *w1, *w2;
    cudaGetSymbolAddress((void**)&h,   g_h);
    cudaGetSymbolAddress((void**)&qkv, g_qkv);
    cudaGetSymbolAddress((void**)&kf,  g_kf);
    cudaGetSymbolAddress((void**)&vf,  g_vf);
    cudaGetSymbolAddress((void**)&o,   g_o);
    cudaGetSymbolAddress((void**)&x1,  g_x1);
    cudaGetSymbolAddress((void**)&hid, g_hid);
    cudaGetSymbolAddress((void**)&wq,  g_wq);
    cudaGetSymbolAddress((void**)&wp,  g_wp);
    cudaGetSymbolAddress((void**)&w1,  g_w1);
    cudaGetSymbolAddress((void**)&w2,  g_w2);

    const int GEMM_SMEM  = 3 * (128 * 20 + 16 * 136) * 4;   // 56832 B
    const int FLASH_SMEM = 2 * 2 * 64 * 68 * 4;             // 69632 B
    cudaFuncSetAttribute((const void*)mma_gemm<true, false, false, true>,
                         cudaFuncAttributeMaxDynamicSharedMemorySize, GEMM_SMEM);
    cudaFuncSetAttribute((const void*)mma_gemm<true, false, true, false>,
                         cudaFuncAttributeMaxDynamicSharedMemorySize, GEMM_SMEM);
    cudaFuncSetAttribute((const void*)mma_gemm<true, true, false, true>,
                         cudaFuncAttributeMaxDynamicSharedMemorySize, GEMM_SMEM);
    cudaFuncSetAttribute(flash_kernel,
                         cudaFuncAttributeMaxDynamicSharedMemorySize, FLASH_SMEM);

    // 0. pre-round weights to tf32
    round_kernel<<<(Cc * C3 / 4) / 256, 256>>>((const float4*)qkv_w, (float4*)wq);
    round_kernel<<<(Cc * Cc / 4) / 256, 256>>>((const float4*)proj_w, (float4*)wp);
    round_kernel<<<(Cc * HIDh / 4) / 256, 256>>>((const float4*)fc1_w, (float4*)w1);
    round_kernel<<<(HIDh * Cc / 4) / 256, 256>>>((const float4*)fc2_w, (float4*)w2);

    // 1. LN1 (rounded out)
    ln_kernel<<<Mtok, 256>>>(x, n1_g, n1_b, h);

    // 2. QKV = h @ wq + qkv_b  (rounded out)
    mma_gemm<true, false, false, true><<<dim3(C3 / 128, Mtok / 128), 256, GEMM_SMEM>>>(
        h, wq, qkv, Cc, Cc, C3, C3, qkv_b, nullptr);

    // 3. mask scan
    p2t_kernel<<<Bb, 32>>>(mask);

    // 4. KV full fill (tf32-rounded)
    kvfill_kernel<<<((Bb * Hh * Nn * HDd) / 4) / 256, 256>>>(
        (const float4*)cachek, (const float4*)cachev);

    // 5-7. fused attention (o rounded out)
    flash_kernel<<<dim3(NPp / 128, Bb * Hh), 256, FLASH_SMEM>>>(qkv, kf, vf, o);

    // 8. x1 = x + o @ wp + proj_b
    mma_gemm<true, false, true, false><<<dim3(Cc / 128, Mtok / 128), 256, GEMM_SMEM>>>(
        o, wp, x1, Cc, Cc, Cc, Cc, proj_b, x);

    // 9. LN2 (rounded out)
    ln_kernel<<<Mtok, 256>>>(x1, n2_g, n2_b, h);

    // 10. hid = gelu(h @ w1 + fc1_b)  (rounded out)
    mma_gemm<true, true, false, true><<<dim3(HIDh / 128, Mtok / 128), 256, GEMM_SMEM>>>(
        h, w1, hid, Cc, Cc, HIDh, HIDh, fc1_b, nullptr);

    // 11. out = x1 + hid @ w2 + fc2_b
    mma_gemm<true, false, true, false><<<dim3(Cc / 128, Mtok / 128), 256, GEMM_SMEM>>>(
        hid, w2, out, HIDh, HIDh, Cc, Cc, fc2_b, x1);
}